// round 1
// baseline (speedup 1.0000x reference)
#include <cuda_runtime.h>
#include <cstdint>

#define NTOT 500000
#define TM 64
#define THREADS 512

#define WSTRIDE 136   // W smem: [128 k][128 n + pad]  -> conflict-free B-frag lds
#define XSTRIDE 136   // X smem: [64 m][128 k + pad]   -> conflict-free A-frag lds
#define YSTRIDE 136   // Y smem: [64 k][128 n + pad]
#define MSTRIDE 68    // M smem: [128 b][64 k + pad]

// smem layout (floats)
#define OFF_WT 0
#define OFF_WG (128 * WSTRIDE)
#define OFF_XM (2 * 128 * WSTRIDE)          // X tile OR mask tile (phase-disjoint), 8704 floats each
#define OFF_Y  (OFF_XM + TM * XSTRIDE)
#define OFF_BT (OFF_Y + TM * YSTRIDE)
#define OFF_BG (OFF_BT + 128)
#define SMEM_FLOATS (OFF_BG + 128)
#define SMEM_BYTES (SMEM_FLOATS * 4)

__device__ __forceinline__ float cvt_tf32(float x) {
    uint32_t u;
    asm("cvt.rna.tf32.f32 %0, %1;" : "=r"(u) : "f"(x));
    return __uint_as_float(u);
}

__device__ __forceinline__ void mma8(float* c,
                                     uint32_t a0, uint32_t a1, uint32_t a2, uint32_t a3,
                                     uint32_t b0, uint32_t b1) {
    asm volatile(
        "mma.sync.aligned.m16n8k8.row.col.f32.tf32.tf32.f32 "
        "{%0,%1,%2,%3}, {%4,%5,%6,%7}, {%8,%9}, {%0,%1,%2,%3};"
        : "+f"(c[0]), "+f"(c[1]), "+f"(c[2]), "+f"(c[3])
        : "r"(a0), "r"(a1), "r"(a2), "r"(a3), "r"(b0), "r"(b1));
}

extern "C" __global__ void zero_out_kernel(float* __restrict__ out) {
    int i = blockIdx.x * blockDim.x + threadIdx.x;
    if (i < 128 * 128) out[i] = 0.0f;
}

extern "C" __global__ void __launch_bounds__(THREADS, 1)
agg_kernel(const float* __restrict__ nodes, const int* __restrict__ masks,
           const float* __restrict__ Wt, const float* __restrict__ bt,
           const float* __restrict__ Wg, const float* __restrict__ bg,
           float* __restrict__ out) {
    extern __shared__ float sm[];
    float* sWt = sm + OFF_WT;
    float* sWg = sm + OFF_WG;
    float* sXM = sm + OFF_XM;
    float* sY  = sm + OFF_Y;
    float* sBt = sm + OFF_BT;
    float* sBg = sm + OFF_BG;

    const int tid  = threadIdx.x;
    const int warp = tid >> 5;
    const int lane = tid & 31;
    const int tg   = lane & 3;   // thread-in-group (k / col selector)
    const int gid  = lane >> 2;  // group id (row selector)

    // Load weights + biases once (tiny: 128 KB of gmem)
    for (int i = tid; i < 128 * 128; i += THREADS) {
        int r = i >> 7, c = i & 127;
        sWt[r * WSTRIDE + c] = Wt[i];
        sWg[r * WSTRIDE + c] = Wg[i];
    }
    if (tid < 128) { sBt[tid] = bt[tid]; sBg[tid] = bg[tid]; }

    // Phase A (input GEMM) warp assignment: m-tile + 32-col slice (data cols and gate cols)
    const int wm = warp & 3;   // node-row tile: rows [16*wm, +16)
    const int wq = warp >> 2;  // col group: cols [32*wq, +32) in both Wt and Wg outputs
    // Phase B (pooling) warp assignment
    const int pm = warp & 7;   // batch-row tile: b in [16*pm, +16)
    const int ph = warp >> 3;  // d-col half: cols [64*ph, +64)

    // Pooling accumulator: persists in registers across ALL tiles
    float pc[8][4];
#pragma unroll
    for (int j = 0; j < 8; j++)
#pragma unroll
        for (int r = 0; r < 4; r++) pc[j][r] = 0.0f;

    const int nTiles = (NTOT + TM - 1) / TM;  // 7813

    for (int t = blockIdx.x; t < nTiles; t += gridDim.x) {
        const int n0 = t * TM;
        __syncthreads();  // prior phase B done reading sXM(mask)/sY; W load visible on first iter

        // ---- Load X tile [64 x 128] (pre-rounded to tf32) ----
        for (int i = tid; i < TM * 128; i += THREADS) {
            int r = i >> 7, c = i & 127;
            int n = n0 + r;
            float v = (n < NTOT) ? nodes[(size_t)n * 128 + c] : 0.0f;
            sXM[r * XSTRIDE + c] = cvt_tf32(v);
        }
        __syncthreads();

        // ---- Phase A: [64x128] @ [128x128]x2 in tf32, W split hi/lo (2 MMA passes) ----
        float accD[4][4], accG[4][4];
#pragma unroll
        for (int j = 0; j < 4; j++)
#pragma unroll
            for (int r = 0; r < 4; r++) { accD[j][r] = 0.0f; accG[j][r] = 0.0f; }

        const int mrow  = wm * 16 + gid;
        const int ncol0 = 32 * wq + gid;
#pragma unroll 2
        for (int ks = 0; ks < 16; ks++) {
            const int k0 = ks * 8 + tg;
            uint32_t a0 = __float_as_uint(sXM[mrow * XSTRIDE + k0]);
            uint32_t a1 = __float_as_uint(sXM[(mrow + 8) * XSTRIDE + k0]);
            uint32_t a2 = __float_as_uint(sXM[mrow * XSTRIDE + k0 + 4]);
            uint32_t a3 = __float_as_uint(sXM[(mrow + 8) * XSTRIDE + k0 + 4]);
#pragma unroll
            for (int j = 0; j < 4; j++) {
                const int n = ncol0 + 8 * j;
                {   // data (Wt)
                    uint32_t w0 = __float_as_uint(sWt[k0 * WSTRIDE + n]);
                    uint32_t w1 = __float_as_uint(sWt[(k0 + 4) * WSTRIDE + n]);
                    uint32_t h0 = w0 & 0xFFFFE000u, h1 = w1 & 0xFFFFE000u;
                    float l0 = __uint_as_float(w0) - __uint_as_float(h0);
                    float l1 = __uint_as_float(w1) - __uint_as_float(h1);
                    mma8(accD[j], a0, a1, a2, a3, h0, h1);
                    mma8(accD[j], a0, a1, a2, a3, __float_as_uint(l0), __float_as_uint(l1));
                }
                {   // gates (Wg)
                    uint32_t w0 = __float_as_uint(sWg[k0 * WSTRIDE + n]);
                    uint32_t w1 = __float_as_uint(sWg[(k0 + 4) * WSTRIDE + n]);
                    uint32_t h0 = w0 & 0xFFFFE000u, h1 = w1 & 0xFFFFE000u;
                    float l0 = __uint_as_float(w0) - __uint_as_float(h0);
                    float l1 = __uint_as_float(w1) - __uint_as_float(h1);
                    mma8(accG[j], a0, a1, a2, a3, h0, h1);
                    mma8(accG[j], a0, a1, a2, a3, __float_as_uint(l0), __float_as_uint(l1));
                }
            }
        }
        __syncthreads();  // all warps done reading sXM -> safe to overwrite with mask

        // ---- Epilogue: y = (data + bt) * sigmoid(gates + bg); store tf32-rounded to sY ----
#pragma unroll
        for (int j = 0; j < 4; j++) {
#pragma unroll
            for (int r = 0; r < 4; r++) {
                int col = 32 * wq + 8 * j + 2 * tg + (r & 1);
                int row = wm * 16 + gid + ((r >> 1) ? 8 : 0);
                float d  = accD[j][r] + sBt[col];
                float gl = accG[j][r] + sBg[col];
                float gate = 1.0f / (1.0f + __expf(-gl));
                sY[row * YSTRIDE + col] = cvt_tf32(d * gate);
            }
        }

        // ---- Load mask tile [128 b x 64 n] as fp32 (0/1 exact in tf32) into sXM ----
        for (int i = tid; i < 128 * TM; i += THREADS) {
            int b = i >> 6, kk = i & 63;
            int n = n0 + kk;
            float mv = (n < NTOT) ? (float)masks[(size_t)b * NTOT + n] : 0.0f;
            sXM[b * MSTRIDE + kk] = mv;
        }
        __syncthreads();

        // ---- Phase B: pool += M[128x64] @ Y[64x128] ----
        const int brow = pm * 16 + gid;
#pragma unroll 2
        for (int ks = 0; ks < 8; ks++) {
            const int kk = ks * 8 + tg;
            uint32_t m0 = __float_as_uint(sXM[brow * MSTRIDE + kk]);
            uint32_t m1 = __float_as_uint(sXM[(brow + 8) * MSTRIDE + kk]);
            uint32_t m2 = __float_as_uint(sXM[brow * MSTRIDE + kk + 4]);
            uint32_t m3 = __float_as_uint(sXM[(brow + 8) * MSTRIDE + kk + 4]);
#pragma unroll
            for (int j = 0; j < 8; j++) {
                const int n = 64 * ph + 8 * j + gid;
                uint32_t y0 = __float_as_uint(sY[kk * YSTRIDE + n]);
                uint32_t y1 = __float_as_uint(sY[(kk + 4) * YSTRIDE + n]);
                mma8(pc[j], m0, m1, m2, m3, y0, y1);
            }
        }
    }

    // ---- Final reduction: one atomicAdd per pooled element per CTA ----
#pragma unroll
    for (int j = 0; j < 8; j++) {
#pragma unroll
        for (int r = 0; r < 4; r++) {
            int b = pm * 16 + gid + ((r >> 1) ? 8 : 0);
            int c = 64 * ph + 8 * j + 2 * tg + (r & 1);
            atomicAdd(&out[b * 128 + c], pc[j][r]);
        }
    }
}

extern "C" void kernel_launch(void* const* d_in, const int* in_sizes, int n_in,
                              void* d_out, int out_size) {
    (void)in_sizes; (void)n_in; (void)out_size;
    const float* nodes = (const float*)d_in[0];
    const int*   masks = (const int*)d_in[1];
    const float* Wt    = (const float*)d_in[2];
    const float* bt    = (const float*)d_in[3];
    const float* Wg    = (const float*)d_in[4];
    const float* bg    = (const float*)d_in[5];
    float* out = (float*)d_out;

    cudaFuncSetAttribute(agg_kernel, cudaFuncAttributeMaxDynamicSharedMemorySize, SMEM_BYTES);

    zero_out_kernel<<<32, 512>>>(out);
    agg_kernel<<<148, THREADS, SMEM_BYTES>>>(nodes, masks, Wt, bt, Wg, bg, out);
}

// round 2
// speedup vs baseline: 2.0710x; 2.0710x over previous
#include <cuda_runtime.h>
#include <cstdint>

#define NTOT 500000
#define TM 64
#define THREADS 512
#define NTILES ((NTOT + TM - 1) / TM)

// smem layout (float offsets). All tiles stride-128, XOR-swizzled (no padding).
#define OFF_WT 0
#define OFF_WG 16384
#define OFF_X  32768
#define OFF_M  40960
#define OFF_Y  49152
#define OFF_BT 57344
#define OFF_BG 57472
#define SMEM_FLOATS 57600
#define SMEM_BYTES (SMEM_FLOATS * 4)   // 230400 B <= 232448 (227 KB)

__device__ __forceinline__ uint32_t cvt_tf32_u(float x) {
    uint32_t u;
    asm("cvt.rna.tf32.f32 %0, %1;" : "=r"(u) : "f"(x));
    return u;
}
__device__ __forceinline__ float cvt_tf32_f(float x) {
    return __uint_as_float(cvt_tf32_u(x));
}

__device__ __forceinline__ void mma8(float* c,
                                     uint32_t a0, uint32_t a1, uint32_t a2, uint32_t a3,
                                     uint32_t b0, uint32_t b1) {
    asm volatile(
        "mma.sync.aligned.m16n8k8.row.col.f32.tf32.tf32.f32 "
        "{%0,%1,%2,%3}, {%4,%5,%6,%7}, {%8,%9}, {%0,%1,%2,%3};"
        : "+f"(c[0]), "+f"(c[1]), "+f"(c[2]), "+f"(c[3])
        : "r"(a0), "r"(a1), "r"(a2), "r"(a3), "r"(b0), "r"(b1));
}

__device__ __forceinline__ void cp16(uint32_t saddr, const void* g, int szbytes) {
    asm volatile("cp.async.cg.shared.global [%0], [%1], 16, %2;"
                 :: "r"(saddr), "l"(g), "r"(szbytes));
}
#define CP_COMMIT() asm volatile("cp.async.commit_group;")
#define CP_WAIT(n)  asm volatile("cp.async.wait_group %0;" :: "n"(n))

extern "C" __global__ void zero_out_kernel(float* __restrict__ out) {
    int i = blockIdx.x * blockDim.x + threadIdx.x;
    if (i < 128 * 128) out[i] = 0.0f;
}

extern "C" __global__ void __launch_bounds__(THREADS, 1)
agg_kernel(const float* __restrict__ nodes, const int* __restrict__ masks,
           const float* __restrict__ Wt, const float* __restrict__ bt,
           const float* __restrict__ Wg, const float* __restrict__ bg,
           float* __restrict__ out) {
    extern __shared__ float sm[];
    float* sWt = sm + OFF_WT;
    float* sWg = sm + OFF_WG;
    float* sX  = sm + OFF_X;
    int*   sM  = (int*)(sm + OFF_M);
    float* sY  = sm + OFF_Y;
    float* sBt = sm + OFF_BT;
    float* sBg = sm + OFF_BG;

    const uint32_t smem_u32 = (uint32_t)__cvta_generic_to_shared(sm);
    const uint32_t sx_u32 = smem_u32 + OFF_X * 4;
    const uint32_t sm_u32 = smem_u32 + OFF_M * 4;

    const int tid  = threadIdx.x;
    const int warp = tid >> 5;
    const int lane = tid & 31;
    const int tg   = lane & 3;   // k/col selector within quad
    const int gid  = lane >> 2;  // row selector

    // W + bias load (once). Pre-round W to tf32 (rna), store XOR-swizzled:
    // w_idx(k,n) = k*128 + (n ^ ((k&3)<<3))
    for (int i = tid; i < 128 * 128; i += THREADS) {
        int k = i >> 7, n = i & 127;
        int idx = (k << 7) + (n ^ ((k & 3) << 3));
        sWt[idx] = cvt_tf32_f(Wt[i]);
        sWg[idx] = cvt_tf32_f(Wg[i]);
    }
    if (tid < 128) { sBt[tid] = bt[tid]; sBg[tid] = bg[tid]; }

    // Phase A warp mapping
    const int wm = warp & 3;          // node-row tile: rows [16*wm, +16)
    const int wq = warp >> 2;         // col group: cols [32*wq, +32)
    // Phase B warp mapping
    const int pm = warp & 7;          // batch-row tile
    const int ph = warp >> 3;         // d-col half

    // Pooling accumulators live in registers across all tiles
    float pc[8][4];
#pragma unroll
    for (int j = 0; j < 8; j++)
#pragma unroll
        for (int r = 0; r < 4; r++) pc[j][r] = 0.0f;

    const int stride = gridDim.x;
    int t = blockIdx.x;

    // ---- prologue: start X(t0) streaming ----
    if (t < NTILES) {
        const int n0 = t * TM;
#pragma unroll
        for (int p = 0; p < 4; p++) {
            int id = tid + THREADS * p;
            int row = id >> 5, ch = id & 31;
            int n = n0 + row;
            const float* g = nodes + (size_t)(n < NTOT ? n : 0) * 128 + ch * 4;
            uint32_t sa = sx_u32 + (((row << 7) + ((ch ^ (row & 7)) << 2)) << 2);
            cp16(sa, g, n < NTOT ? 16 : 0);
        }
    }
    CP_COMMIT();

    for (; t < NTILES; t += stride) {
        const int n0 = t * TM;

        CP_WAIT(0);          // X(t) landed
        __syncthreads();     // all warps past phase B(t-1); X(t) visible

        // ---- start mask(t) streaming (overlaps all of phase A) ----
#pragma unroll
        for (int p = 0; p < 4; p++) {
            int id = tid + THREADS * p;
            int b = id >> 4, ch = id & 15;
            int n = n0 + ch * 4;
            const int* g = masks + (size_t)b * NTOT + (n < NTOT ? n : 0);
            uint32_t sa = sm_u32 + ((((b << 6) + ((ch ^ (b & 7)) << 2))) << 2);
            cp16(sa, g, n < NTOT ? 16 : 0);
        }
        CP_COMMIT();

        // ---- Phase A: [64x128] @ [128x128] x2, single tf32 pass each ----
        float accD[4][4], accG[4][4];
#pragma unroll
        for (int j = 0; j < 4; j++)
#pragma unroll
            for (int r = 0; r < 4; r++) { accD[j][r] = 0.0f; accG[j][r] = 0.0f; }

        const int mrow  = wm * 16 + gid;
        const int ncol0 = 32 * wq + gid;
        const int xsw   = gid << 2;       // X swizzle ((row&7)<<2), rows mrow/mrow+8 share it
        const int wsw   = tg << 3;        // W/Y swizzle ((k&3)<<3), k0 and k0+4 share it

#pragma unroll 4
        for (int ks = 0; ks < 16; ks++) {
            const int k0 = ks * 8 + tg;
            uint32_t a0 = cvt_tf32_u(sX[(mrow << 7)       + (k0 ^ xsw)]);
            uint32_t a1 = cvt_tf32_u(sX[((mrow + 8) << 7) + (k0 ^ xsw)]);
            uint32_t a2 = cvt_tf32_u(sX[(mrow << 7)       + ((k0 + 4) ^ xsw)]);
            uint32_t a3 = cvt_tf32_u(sX[((mrow + 8) << 7) + ((k0 + 4) ^ xsw)]);
            const int base0 = k0 << 7;
            const int base1 = (k0 + 4) << 7;
#pragma unroll
            for (int j = 0; j < 4; j++) {
                const int cidx = (ncol0 + 8 * j) ^ wsw;
                uint32_t d0 = __float_as_uint(sWt[base0 + cidx]);
                uint32_t d1 = __float_as_uint(sWt[base1 + cidx]);
                mma8(accD[j], a0, a1, a2, a3, d0, d1);
                uint32_t g0 = __float_as_uint(sWg[base0 + cidx]);
                uint32_t g1 = __float_as_uint(sWg[base1 + cidx]);
                mma8(accG[j], a0, a1, a2, a3, g0, g1);
            }
        }
        __syncthreads();   // phase A done reading sX

        // ---- start X(t+stride) streaming (overlaps epilogue + phase B) ----
        {
            const int tn = t + stride;
            if (tn < NTILES) {
                const int nn0 = tn * TM;
#pragma unroll
                for (int p = 0; p < 4; p++) {
                    int id = tid + THREADS * p;
                    int row = id >> 5, ch = id & 31;
                    int n = nn0 + row;
                    const float* g = nodes + (size_t)(n < NTOT ? n : 0) * 128 + ch * 4;
                    uint32_t sa = sx_u32 + (((row << 7) + ((ch ^ (row & 7)) << 2)) << 2);
                    cp16(sa, g, n < NTOT ? 16 : 0);
                }
            }
            CP_COMMIT();
        }

        // ---- Epilogue: y = (d + bt) * sigmoid(g + bg), tf32-rounded into sY ----
#pragma unroll
        for (int j = 0; j < 4; j++) {
#pragma unroll
            for (int r = 0; r < 4; r++) {
                int col = 32 * wq + 8 * j + 2 * tg + (r & 1);
                int row = wm * 16 + gid + ((r >> 1) ? 8 : 0);
                float d  = accD[j][r] + sBt[col];
                float gl = accG[j][r] + sBg[col];
                float gate = 1.0f / (1.0f + __expf(-gl));
                sY[(row << 7) + (col ^ ((row & 3) << 3))] = cvt_tf32_f(d * gate);
            }
        }

        CP_WAIT(1);        // mask(t) landed (X(t+1) may still be in flight)
        __syncthreads();   // Y + mask visible to all

        // ---- Phase B: pool += M[128x64] @ Y[64x128] ----
        const int brow = pm * 16 + gid;
        const int msw  = gid << 2;   // mask swizzle ((b&7)<<2), brow/brow+8 share it
#pragma unroll 4
        for (int ks = 0; ks < 8; ks++) {
            const int kk = ks * 8 + tg;
            uint32_t m0 = __float_as_uint((float)sM[(brow << 6)       + (kk ^ msw)]);
            uint32_t m1 = __float_as_uint((float)sM[((brow + 8) << 6) + (kk ^ msw)]);
            uint32_t m2 = __float_as_uint((float)sM[(brow << 6)       + ((kk + 4) ^ msw)]);
            uint32_t m3 = __float_as_uint((float)sM[((brow + 8) << 6) + ((kk + 4) ^ msw)]);
            const int yb0 = kk << 7;
            const int yb1 = (kk + 4) << 7;
#pragma unroll
            for (int j = 0; j < 8; j++) {
                const int cidx = (64 * ph + 8 * j + gid) ^ wsw;
                uint32_t y0 = __float_as_uint(sY[yb0 + cidx]);
                uint32_t y1 = __float_as_uint(sY[yb1 + cidx]);
                mma8(pc[j], m0, m1, m2, m3, y0, y1);
            }
        }
    }

    // ---- Final reduction: one atomicAdd per pooled element per CTA ----
#pragma unroll
    for (int j = 0; j < 8; j++) {
#pragma unroll
        for (int r = 0; r < 4; r++) {
            int b = pm * 16 + gid + ((r >> 1) ? 8 : 0);
            int c = 64 * ph + 8 * j + 2 * tg + (r & 1);
            atomicAdd(&out[b * 128 + c], pc[j][r]);
        }
    }
}

extern "C" void kernel_launch(void* const* d_in, const int* in_sizes, int n_in,
                              void* d_out, int out_size) {
    (void)in_sizes; (void)n_in; (void)out_size;
    const float* nodes = (const float*)d_in[0];
    const int*   masks = (const int*)d_in[1];
    const float* Wt    = (const float*)d_in[2];
    const float* bt    = (const float*)d_in[3];
    const float* Wg    = (const float*)d_in[4];
    const float* bg    = (const float*)d_in[5];
    float* out = (float*)d_out;

    cudaFuncSetAttribute(agg_kernel, cudaFuncAttributeMaxDynamicSharedMemorySize, SMEM_BYTES);

    zero_out_kernel<<<32, 512>>>(out);
    agg_kernel<<<148, THREADS, SMEM_BYTES>>>(nodes, masks, Wt, bt, Wg, bg, out);
}